// round 16
// baseline (speedup 1.0000x reference)
#include <cuda_runtime.h>

#define Bdim 4
#define Ldim 512
#define Ddim 128
#define Hdim 128
#define G4   512            // 4*H
#define NROWS (Bdim*Ldim)   // 2048
#define EPSV 1e-5f
#define CH   8              // pipeline chunk (timesteps)
#define NATT 88             // attention-worker CTAs (total grid 136 CTAs = 68 clusters)
#define NWRK (NATT*4)       // 128-thread worker groups (352)

// ---------------- scratch (device globals; no allocation) ----------------
__device__ float g_q[NROWS*Ddim];
__device__ float g_k[NROWS*Ddim];
__device__ float g_v[NROWS*Ddim];
__device__ float g_attn[NROWS*Ddim];
__device__ float g_bnscale[3][Ddim];
__device__ float g_bnshift[3][Ddim];
__device__ float g_U[3][NROWS*G4];
__device__ float g_h1[3][NROWS*Hdim];
__device__ float g_h2[3][NROWS*Hdim];
__device__ unsigned g_prog[3][Bdim];       // layer-0 scan progress per (br,b)
__device__ unsigned g_part_done;           // bn partial slots written (0..NWRK)
__device__ unsigned g_bn_done;             // br1/2 bn scale/shift ready
__device__ unsigned g_uproj_cnt;           // attn CTAs finished uproj (0..NATT)
__device__ float g_bnpart[4][NWRK*Ddim];   // [stat][worker*128+c]; 0,1=br1 S,Q 2,3=br2
// transposed weights: [layer][branch][k4*512 + j] (k-major, gate j lane-contiguous)
__device__ float g_wtih[2][3][G4*Ddim];
__device__ float g_wthh[2][3][G4*Hdim];

// ---------------- helpers ----------------
__device__ __forceinline__ float fast_tanh(float x) {
    float e = __expf(2.f * x);
    return 1.f - __fdividef(2.f, e + 1.f);
}
__device__ __forceinline__ float fast_sigmoid(float x) {
    return __fdividef(1.f, 1.f + __expf(-x));
}
__device__ __forceinline__ unsigned long long ffma2(unsigned long long a,
                                                    unsigned long long b,
                                                    unsigned long long c) {
    unsigned long long d;
    asm("fma.rn.f32x2 %0, %1, %2, %3;" : "=l"(d) : "l"(a), "l"(b), "l"(c));
    return d;
}
__device__ __forceinline__ float pairsum(unsigned long long d) {
    float lo = __uint_as_float((unsigned)(d & 0xffffffffull));
    float hi = __uint_as_float((unsigned)(d >> 32));
    return lo + hi;
}
__device__ __forceinline__ unsigned int smem_u32(const void* p) {
    return (unsigned int)__cvta_generic_to_shared(p);
}
__device__ __forceinline__ void gbar(int id) {
    asm volatile("bar.sync %0, 128;" :: "r"(id) : "memory");
}
// group (128-thread) reductions via shfl + 4-slot smem + named barrier
__device__ __forceinline__ float gsum(float v, float* rb, int lane, int wig, int id) {
    #pragma unroll
    for (int m = 16; m > 0; m >>= 1) v += __shfl_xor_sync(0xffffffffu, v, m);
    if (lane == 0) rb[wig] = v;
    gbar(id);
    v = rb[0] + rb[1] + rb[2] + rb[3];
    gbar(id);
    return v;
}
__device__ __forceinline__ float gmaxr(float v, float* rb, int lane, int wig, int id) {
    #pragma unroll
    for (int m = 16; m > 0; m >>= 1) v = fmaxf(v, __shfl_xor_sync(0xffffffffu, v, m));
    if (lane == 0) rb[wig] = v;
    gbar(id);
    v = fmaxf(fmaxf(rb[0], rb[1]), fmaxf(rb[2], rb[3]));
    gbar(id);
    return v;
}
// block reductions for 128 threads (final_kernel)
__device__ __forceinline__ float bredsum(float v, float* buf) {
    int tid = threadIdx.x;
    buf[tid] = v; __syncthreads();
    #pragma unroll
    for (int s = 64; s > 0; s >>= 1) {
        if (tid < s) buf[tid] += buf[tid + s];
        __syncthreads();
    }
    float r = buf[0]; __syncthreads();
    return r;
}

// role-overlayed shared memory: each CTA uses exactly one member.
// scan = 27,648 B; attn = 30,784 B; union = 30,784 B (< 48 KB static limit).
union __align__(16) SmemU {
    struct {
        float hs[Hdim];
        float cs[Hdim];
        float sp[512];
        float zact[2][G4];
        float h1c[CH][Hdim];
        float upart[CH][512];
    } scan;
    struct {
        float xi[4][Ddim];
        float qi[4][Ddim];
        float s1[4][Ldim];
        float s2[4][Ldim];
        float s3[4][Ldim];
        float rb[4][4];
        float uxs[4][Ddim];
    } attn;
};

// ---------------- kernel 0: weight transpose + flag reset ----------------
// grid (32, 12), block 512.
__global__ void transpose_kernel(const float* __restrict__ w1i, const float* __restrict__ w1h,
                                 const float* __restrict__ w2i, const float* __restrict__ w2h,
                                 const float* __restrict__ w3i, const float* __restrict__ w3h) {
    if (blockIdx.y == 0 && blockIdx.x == 0 && threadIdx.x < 32) {
        int t = threadIdx.x;
        if (t < 12) ((unsigned*)g_prog)[t] = 0u;
        if (t == 12) g_part_done = 0u;
        if (t == 13) g_bn_done = 0u;
        if (t == 14) g_uproj_cnt = 0u;
    }
    int m = blockIdx.y;
    int type = m / 6;
    int r = m % 6;
    int layer = r / 3;
    int br = r % 3;
    const float* W;
    if (type == 0) W = ((br == 0) ? w1i : (br == 1) ? w2i : w3i) + layer * G4 * Ddim;
    else           W = ((br == 0) ? w1h : (br == 1) ? w2h : w3h) + layer * G4 * Hdim;
    float* out = (type == 0) ? g_wtih[layer][br] : g_wthh[layer][br];
    int linear = blockIdx.x * 512 + threadIdx.x;
    int k4 = linear >> 9;
    int j = linear & 511;
    float4 v = *(const float4*)(W + j * Ddim + 4 * k4);
    ((float4*)out)[linear] = v;
}

// ---------------- kernel 1: q/k/v projections ----------------
__global__ void qkv_kernel(const float* __restrict__ x,
                           const float* __restrict__ Wq,
                           const float* __restrict__ Wk,
                           const float* __restrict__ bk,
                           const float* __restrict__ Wv) {
    int mat = blockIdx.y;
    const float* W = (mat == 0) ? Wq : (mat == 1) ? Wk : Wv;
    float* out = (mat == 0) ? g_q : (mat == 1) ? g_k : g_v;
    int row0 = blockIdx.x * 8;
    int tid = threadIdx.x;
    __shared__ __align__(16) float xs[8][Ddim];
    #pragma unroll
    for (int r = 0; r < 8; r++) xs[r][tid] = x[(row0 + r) * Ddim + tid];
    __syncthreads();
    float acc[8] = {0, 0, 0, 0, 0, 0, 0, 0};
    const float4* w4 = (const float4*)(W + tid * Ddim);
    #pragma unroll 8
    for (int k4 = 0; k4 < 32; k4++) {
        float4 w = w4[k4];
        #pragma unroll
        for (int r = 0; r < 8; r++) {
            float4 xv = ((const float4*)xs[r])[k4];
            acc[r] += xv.x * w.x + xv.y * w.y + xv.z * w.z + xv.w * w.w;
        }
    }
    float bb = (mat == 1) ? bk[tid] : 0.f;
    #pragma unroll
    for (int r = 0; r < 8; r++) out[(row0 + r) * Ddim + tid] = acc[r] + bb;
}

// ---------------- kernel 3: batchnorm stats (branch 0 only) ----------------
// grid (128, 1), block 256.
__global__ void bnstat_kernel(const float* __restrict__ x,
                              const float* __restrict__ g1, const float* __restrict__ b1) {
    int c = blockIdx.x, tid = threadIdx.x;
    float s = 0.f, ss = 0.f;
    for (int n = tid; n < NROWS; n += 256) {
        float v = x[n * Ddim + c];
        s += v; ss += v * v;
    }
    __shared__ float bs[256], bss[256];
    bs[tid] = s; bss[tid] = ss; __syncthreads();
    #pragma unroll
    for (int st = 128; st > 0; st >>= 1) {
        if (tid < st) { bs[tid] += bs[tid + st]; bss[tid] += bss[tid + st]; }
        __syncthreads();
    }
    if (tid == 0) {
        float m = bs[0] * (1.f / NROWS);
        float var = bss[0] * (1.f / NROWS) - m * m;
        float rstd = rsqrtf(var + EPSV);
        float sc = rstd * g1[c];
        g_bnscale[0][c] = sc;
        g_bnshift[0][c] = b1[c] - m * sc;
    }
}

// ---------------- kernel 4: branch-0 layer-0 input projection ----------------
// grid (512, 1), block 512.
__global__ void __launch_bounds__(512)
uproj_kernel(const float* __restrict__ x,
             const float* __restrict__ bih0, const float* __restrict__ bhh0) {
    const float4* wt = (const float4*)g_wtih[0][0];
    float* U = g_U[0];
    int row0 = blockIdx.x * 4;
    int tid = threadIdx.x;
    __shared__ __align__(16) float xs[4][Ddim];
    {
        int r = tid >> 7, c = tid & 127;
        float xv = x[(row0 + r) * Ddim + c];
        xs[r][c] = xv * g_bnscale[0][c] + g_bnshift[0][c];
    }
    __syncthreads();
    int j = tid;
    float acc[4] = {0, 0, 0, 0};
    #pragma unroll 8
    for (int k4 = 0; k4 < 32; k4++) {
        float4 w = wt[k4 * 512 + j];
        #pragma unroll
        for (int r = 0; r < 4; r++) {
            float4 h = ((const float4*)xs[r])[k4];
            acc[r] += w.x * h.x + w.y * h.y + w.z * h.z + w.w * h.w;
        }
    }
    float bias = bih0[j] + bhh0[j];
    #pragma unroll
    for (int r = 0; r < 4; r++) U[(row0 + r) * G4 + j] = acc[r] + bias;
}

// ---------------- MEGA kernel: scans (z<6) + attention/bn/uproj workers (z>=6) --------
// grid (2, 4, 17), cluster (2,1,1), block 512. 136 CTAs = 68 clusters (fits one wave).
__global__ void __cluster_dims__(2, 1, 1) __launch_bounds__(512, 1)
mega_kernel(const float* __restrict__ x,
            const float* __restrict__ attn_w, const float* __restrict__ attn_scale,
            const float* __restrict__ bn2g, const float* __restrict__ bn2b,
            const float* __restrict__ bn3g, const float* __restrict__ bn3b,
            const float* __restrict__ bih0, const float* __restrict__ bhh0,
            const float* __restrict__ bih1, const float* __restrict__ bhh1,
            const float* __restrict__ bih2, const float* __restrict__ bhh2) {
    int tid = threadIdx.x;
    int zb = blockIdx.z;
    __shared__ SmemU su;

    if (zb < 6) {
        // ================= SCAN ROLE (R14 fused pipelined scan) =================
        unsigned int rank;
        asm("mov.u32 %0, %%cluster_ctarank;" : "=r"(rank));
        int b = blockIdx.y;
        int br = zb % 3, lay = zb / 3;
        const ulonglong2* wt = (const ulonglong2*)g_wthh[lay][br];
        const float* U = g_U[br] + b * Ldim * G4;
        const float* h1g = g_h1[br] + b * Ldim * Hdim;
        float* hout = ((lay == 0) ? g_h1[br] : g_h2[br]) + b * Ldim * Hdim;
        int gate = tid & 255;
        int half = tid >> 8;
        int jg = (int)rank * 256 + gate;
        unsigned int peer = rank ^ 1u;

        float* hs = su.scan.hs;
        float* cs = su.scan.cs;
        float* sp = su.scan.sp;

        if (tid < Hdim) { hs[tid] = 0.f; cs[tid] = 0.f; }

        ulonglong2 wreg[16];
        #pragma unroll
        for (int m = 0; m < 16; m++) wreg[m] = wt[(half * 16 + m) * 512 + jg];

        float biasr = 0.f;
        if (lay == 1 && tid < 256) {
            const float* bi = ((br == 0) ? bih0 : (br == 1) ? bih1 : bih2);
            const float* bh = ((br == 0) ? bhh0 : (br == 1) ? bhh1 : bhh2);
            biasr = bi[G4 + jg] + bh[G4 + jg];
        }
        const ulonglong2* wih = (const ulonglong2*)g_wtih[1][br];

        // br1/2 layer-0 waits for uproj workers
        if (lay == 0 && br != 0) {
            if (tid == 0) {
                while (atomicAdd(&g_uproj_cnt, 0u) < (unsigned)NATT) {}
                __threadfence();
            }
        }
        __syncthreads();

        for (int c = 0; c < Ldim / CH; c++) {
            if (lay == 1) {
                if (tid == 0) {
                    unsigned target = (unsigned)((c + 1) * CH);
                    while (atomicAdd(&g_prog[br][b], 0u) < target) {}
                    __threadfence();
                }
                __syncthreads();
                if (tid < CH * 32)
                    ((float4*)su.scan.h1c)[tid] = ((const float4*)(h1g + c * CH * Hdim))[tid];
                __syncthreads();
                unsigned long long a0[CH], a1[CH];
                #pragma unroll
                for (int t = 0; t < CH; t++) { a0[t] = 0ull; a1[t] = 0ull; }
                #pragma unroll
                for (int m = 0; m < 16; m++) {
                    ulonglong2 wv = wih[(half * 16 + m) * 512 + jg];
                    #pragma unroll
                    for (int t = 0; t < CH; t++) {
                        const ulonglong2* hv = (const ulonglong2*)(su.scan.h1c[t] + half * 64);
                        ulonglong2 h = hv[m];
                        a0[t] = ffma2(wv.x, h.x, a0[t]);
                        a1[t] = ffma2(wv.y, h.y, a1[t]);
                    }
                }
                #pragma unroll
                for (int t = 0; t < CH; t++)
                    su.scan.upart[t][tid] = pairsum(a0[t]) + pairsum(a1[t]);
                __syncthreads();
            }

            for (int tt = 0; tt < CH; tt++) {
                int t = c * CH + tt;
                int buf = t & 1;
                float u = 0.f;
                if (lay == 0 && tid < 256) u = U[t * G4 + (int)rank * 256 + tid];
                const ulonglong2* hv = (const ulonglong2*)(hs + half * 64);
                unsigned long long d0 = 0ull, d1 = 0ull, d2 = 0ull, d3 = 0ull;
                #pragma unroll
                for (int m = 0; m < 16; m += 4) {
                    d0 = ffma2(wreg[m+0].x, hv[m+0].x, d0);
                    d1 = ffma2(wreg[m+0].y, hv[m+0].y, d1);
                    d2 = ffma2(wreg[m+1].x, hv[m+1].x, d2);
                    d3 = ffma2(wreg[m+1].y, hv[m+1].y, d3);
                    d0 = ffma2(wreg[m+2].x, hv[m+2].x, d0);
                    d1 = ffma2(wreg[m+2].y, hv[m+2].y, d1);
                    d2 = ffma2(wreg[m+3].x, hv[m+3].x, d2);
                    d3 = ffma2(wreg[m+3].y, hv[m+3].y, d3);
                }
                float dp = pairsum(d0) + pairsum(d1) + pairsum(d2) + pairsum(d3);
                sp[tid] = dp + ((lay == 1) ? su.scan.upart[tt][tid] : u);
                __syncthreads();
                if (tid < 256) {
                    float zv = sp[tid] + sp[tid + 256] + biasr;
                    float a = (jg >= 256 && jg < 384) ? fast_tanh(zv) : fast_sigmoid(zv);
                    int zl = (int)rank * 256 + tid;
                    su.scan.zact[buf][zl] = a;
                    unsigned int la = smem_u32(&su.scan.zact[buf][zl]);
                    unsigned int ra;
                    asm volatile("mapa.shared::cluster.u32 %0, %1, %2;"
                                 : "=r"(ra) : "r"(la), "r"(peer));
                    asm volatile("st.shared::cluster.f32 [%0], %1;"
                                 :: "r"(ra), "f"(a) : "memory");
                }
                asm volatile("barrier.cluster.arrive.aligned;" ::: "memory");
                asm volatile("barrier.cluster.wait.aligned;" ::: "memory");
                if (tid < Hdim) {
                    float ai = su.scan.zact[buf][tid],       af = su.scan.zact[buf][128 + tid];
                    float ag = su.scan.zact[buf][256 + tid], ao = su.scan.zact[buf][384 + tid];
                    float cn = af * cs[tid] + ai * ag;
                    float hn = ao * fast_tanh(cn);
                    cs[tid] = cn;
                    hs[tid] = hn;
                    if (rank == 0) hout[t * Hdim + tid] = hn;
                }
                __syncthreads();
            }

            if (lay == 0 && rank == 0) {
                __threadfence();
                __syncthreads();
                if (tid == 0) atomicExch(&g_prog[br][b], (unsigned)((c + 1) * CH));
            }
        }
        return;
    }

    // ================= ATTENTION / BN / UPROJ WORKER ROLE =================
    int ctaIdx = ((zb - 6) * 4 + blockIdx.y) * 2 + blockIdx.x;   // 0..NATT-1
    int g = tid >> 7;          // group 0..3
    int t = tid & 127;
    int lane = tid & 31;
    int wig = (tid >> 5) & 3;
    int w = ctaIdx * 4 + g;    // worker 0..NWRK-1
    int barid = g + 1;

    float sc2 = attn_scale[0] * rsqrtf((float)Ddim);
    float w0 = attn_w[0], w1 = attn_w[1], w2 = attn_w[2];
    float winv = 1.f / (w0 + w1 + w2);

    float sA = 0.f, qA = 0.f, sB = 0.f, qB = 0.f;   // bn partials (br1: x+a, br2: a)

    for (int idx = w; idx < NROWS; idx += NWRK) {
        int b = idx >> 9, i = idx & 511;
        const float* xb = x + b * Ldim * Ddim;
        const float* qb = g_q + b * Ldim * Ddim;
        const float* kb = g_k + b * Ldim * Ddim;
        const float* vb = g_v + b * Ldim * Ddim;

        su.attn.xi[g][t] = xb[i * Ddim + t];
        su.attn.qi[g][t] = qb[i * Ddim + t];
        gbar(barid);

        float4 xiv4 = ((const float4*)su.attn.xi[g])[lane];
        float4 qiv4 = ((const float4*)su.attn.qi[g])[lane];
        for (int j = wig; j <= i; j += 4) {
            float4 xv = ((const float4*)(xb + j * Ddim))[lane];
            float4 kv = ((const float4*)(kb + j * Ddim))[lane];
            float a1 = xiv4.x * xv.x + xiv4.y * xv.y + xiv4.z * xv.z + xiv4.w * xv.w;
            float a2 = qiv4.x * kv.x + qiv4.y * kv.y + qiv4.z * kv.z + qiv4.w * kv.w;
            float a3 = fast_tanh(xiv4.x + xv.x) + fast_tanh(xiv4.y + xv.y)
                     + fast_tanh(xiv4.z + xv.z) + fast_tanh(xiv4.w + xv.w);
            #pragma unroll
            for (int m = 16; m > 0; m >>= 1) {
                a1 += __shfl_xor_sync(0xffffffffu, a1, m);
                a2 += __shfl_xor_sync(0xffffffffu, a2, m);
                a3 += __shfl_xor_sync(0xffffffffu, a3, m);
            }
            if (lane == 0) {
                su.attn.s1[g][j] = a1;
                su.attn.s2[g][j] = a2 * sc2;
                su.attn.s3[g][j] = a3;
            }
        }
        gbar(barid);

        float m1 = -1e30f, m2 = -1e30f, m3 = -1e30f;
        for (int j = t; j <= i; j += 128) {
            m1 = fmaxf(m1, su.attn.s1[g][j]);
            m2 = fmaxf(m2, su.attn.s2[g][j]);
            m3 = fmaxf(m3, su.attn.s3[g][j]);
        }
        m1 = gmaxr(m1, su.attn.rb[g], lane, wig, barid);
        m2 = gmaxr(m2, su.attn.rb[g], lane, wig, barid);
        m3 = gmaxr(m3, su.attn.rb[g], lane, wig, barid);

        float t1 = 0.f, t2 = 0.f, t3 = 0.f;
        for (int j = t; j <= i; j += 128) {
            float e1 = __expf(su.attn.s1[g][j] - m1); su.attn.s1[g][j] = e1; t1 += e1;
            float e2 = __expf(su.attn.s2[g][j] - m2); su.attn.s2[g][j] = e2; t2 += e2;
            float e3 = __expf(su.attn.s3[g][j] - m3); su.attn.s3[g][j] = e3; t3 += e3;
        }
        float S1 = gsum(t1, su.attn.rb[g], lane, wig, barid);
        float S2 = gsum(t2, su.attn.rb[g], lane, wig, barid);
        float S3 = gsum(t3, su.attn.rb[g], lane, wig, barid);

        float c1 = 0.f, c2 = 0.f, c3 = 0.f;
        const float* xcol = xb + t;
        const float* vcol = vb + t;
        #pragma unroll 4
        for (int j = 0; j <= i; j++) {
            float p1 = su.attn.s1[g][j], p2 = su.attn.s2[g][j], p3 = su.attn.s3[g][j];
            float xv = xcol[j * Ddim];
            float vv = vcol[j * Ddim];
            c1 += p1 * xv;
            c2 += p2 * vv;
            c3 += p3 * xv;
        }
        float o = (w0 * c1 / S1 + w1 * c2 / S2 + w2 * c3 / S3) * winv;
        g_attn[(b * Ldim + i) * Ddim + t] = o;
        float v1 = su.attn.xi[g][t] + o;
        sA += v1; qA += v1 * v1; sB += o; qB += o * o;
        gbar(barid);
    }

    // deterministic bn partials
    g_bnpart[0][w * Ddim + t] = sA;
    g_bnpart[1][w * Ddim + t] = qA;
    g_bnpart[2][w * Ddim + t] = sB;
    g_bnpart[3][w * Ddim + t] = qB;
    __threadfence();
    gbar(barid);
    if (t == 0) atomicAdd(&g_part_done, 1u);

    __syncthreads();
    if (ctaIdx == 0) {
        if (tid == 0) {
            while (atomicAdd(&g_part_done, 0u) < (unsigned)NWRK) {}
            __threadfence();
        }
        __syncthreads();
        if (tid < 256) {
            int c = tid & 127, sel = tid >> 7;          // 0 -> br1, 1 -> br2
            float S = 0.f, Q = 0.f;
            for (int ww = 0; ww < NWRK; ww++) {
                S += g_bnpart[sel * 2][ww * Ddim + c];
                Q += g_bnpart[sel * 2 + 1][ww * Ddim + c];
            }
            float m = S * (1.f / NROWS);
            float var = Q * (1.f / NROWS) - m * m;
            float rstd = rsqrtf(var + EPSV);
            const float* gg = sel ? bn3g : bn2g;
            const float* bb = sel ? bn3b : bn2b;
            float sc = rstd * gg[c];
            g_bnscale[1 + sel][c] = sc;
            g_bnshift[1 + sel][c] = bb[c] - m * sc;
        }
        __threadfence();
        __syncthreads();
        if (tid == 0) atomicExch(&g_bn_done, 1u);
    }
    if (tid == 0) {
        while (atomicAdd(&g_bn_done, 0u) == 0u) {}
        __threadfence();
    }
    __syncthreads();

    // uproj units for br1/br2 (fixed assignment, deterministic)
    for (int u = ctaIdx; u < 1024; u += NATT) {
        int br = 1 + (u >> 9);
        int row0 = (u & 511) * 4;
        const float4* wtp = (const float4*)g_wtih[0][br];
        const float* bi = (br == 1) ? bih1 : bih2;
        const float* bh = (br == 1) ? bhh1 : bhh2;
        {
            int r = tid >> 7, c = tid & 127;
            float xv = x[(row0 + r) * Ddim + c];
            float av = g_attn[(row0 + r) * Ddim + c];
            float in = (br == 1) ? (xv + av) : av;
            su.attn.uxs[r][c] = in * g_bnscale[br][c] + g_bnshift[br][c];
        }
        __syncthreads();
        float acc[4] = {0, 0, 0, 0};
        #pragma unroll 8
        for (int k4 = 0; k4 < 32; k4++) {
            float4 wv = wtp[k4 * 512 + tid];
            #pragma unroll
            for (int r = 0; r < 4; r++) {
                float4 h = ((const float4*)su.attn.uxs[r])[k4];
                acc[r] += wv.x * h.x + wv.y * h.y + wv.z * h.z + wv.w * h.w;
            }
        }
        float bias = bi[tid] + bh[tid];
        #pragma unroll
        for (int r = 0; r < 4; r++) g_U[br][(row0 + r) * G4 + tid] = acc[r] + bias;
        __syncthreads();
    }
    __threadfence();
    __syncthreads();
    if (tid == 0) atomicAdd(&g_uproj_cnt, 1u);
}

// ---------------- kernel 6: weighted sum + layernorm ----------------
__global__ void final_kernel(const float* __restrict__ sum_w,
                             const float* __restrict__ ln_g,
                             const float* __restrict__ ln_b,
                             float* __restrict__ out) {
    int row = blockIdx.x, tid = threadIdx.x;
    float w0 = sum_w[0], w1 = sum_w[1], w2 = sum_w[2];
    float inv = 1.f / (w0 + w1 + w2);
    float v = (w0 * g_h2[0][row * Hdim + tid]
             + w1 * g_h2[1][row * Hdim + tid]
             + w2 * g_h2[2][row * Hdim + tid]) * inv;
    __shared__ float buf[128];
    float m = bredsum(v, buf) * (1.f / Hdim);
    float d = v - m;
    float var = bredsum(d * d, buf) * (1.f / Hdim);
    out[row * Hdim + tid] = d * rsqrtf(var + EPSV) * ln_g[tid] + ln_b[tid];
}

// ---------------- launch ----------------
extern "C" void kernel_launch(void* const* d_in, const int* in_sizes, int n_in,
                              void* d_out, int out_size) {
    const float* x          = (const float*)d_in[0];
    const float* attn_w     = (const float*)d_in[1];
    const float* attn_scale = (const float*)d_in[2];
    const float* Wq         = (const float*)d_in[3];
    const float* Wk         = (const float*)d_in[4];
    const float* bk         = (const float*)d_in[5];
    const float* Wv         = (const float*)d_in[6];
    const float* bn1g = (const float*)d_in[7],  *bn1b = (const float*)d_in[8];
    const float* bn2g = (const float*)d_in[9],  *bn2b = (const float*)d_in[10];
    const float* bn3g = (const float*)d_in[11], *bn3b = (const float*)d_in[12];
    const float* l1_Wih = (const float*)d_in[13], *l1_Whh = (const float*)d_in[14];
    const float* l1_bih = (const float*)d_in[15], *l1_bhh = (const float*)d_in[16];
    const float* l2_Wih = (const float*)d_in[17], *l2_Whh = (const float*)d_in[18];
    const float* l2_bih = (const float*)d_in[19], *l2_bhh = (const float*)d_in[20];
    const float* l3_Wih = (const float*)d_in[21], *l3_Whh = (const float*)d_in[22];
    const float* l3_bih = (const float*)d_in[23], *l3_bhh = (const float*)d_in[24];
    const float* ln_g  = (const float*)d_in[25];
    const float* ln_b  = (const float*)d_in[26];
    const float* sum_w = (const float*)d_in[27];
    float* out = (float*)d_out;

    transpose_kernel<<<dim3(32, 12), 512>>>(l1_Wih, l1_Whh, l2_Wih, l2_Whh, l3_Wih, l3_Whh);
    qkv_kernel<<<dim3(256, 3), 128>>>(x, Wq, Wk, bk, Wv);
    bnstat_kernel<<<dim3(128, 1), 256>>>(x, bn1g, bn1b);
    uproj_kernel<<<dim3(512, 1), 512>>>(x, l1_bih, l1_bhh);
    mega_kernel<<<dim3(2, Bdim, 17), 512>>>(
        x, attn_w, attn_scale, bn2g, bn2b, bn3g, bn3b,
        l1_bih, l1_bhh, l2_bih, l2_bhh, l3_bih, l3_bhh);
    final_kernel<<<NROWS, 128>>>(sum_w, ln_g, ln_b, out);
}